// round 1
// baseline (speedup 1.0000x reference)
#include <cuda_runtime.h>
#include <math.h>
#include <float.h>

#define BB 32
#define NPG0 4096
#define DEGV 16
#define HIDV 16
#define OUTD 23
#define N0 131072
#define E_TOT (N0*DEGV)
#define KK1 2458
#define NN1 (BB*KK1)
#define KK2 1475
#define NN2 (BB*KK2)
#define KK3 885
#define NN3 (BB*KK3)
#define DIVC 1.0e-4f

// ------------------ scratch (device globals; no allocation allowed) --------
__device__ float g_h24[N0*24];
__device__ float g_hd [N0*16];
__device__ float g_hA [N0*16];
__device__ float g_hB [N0*16];
__device__ float g_dinv[N0];
__device__ int   g_esrc[E_TOT];
__device__ int   g_edst[E_TOT];
__device__ int   g_col [E_TOT];
__device__ int   g_coff[N0];
__device__ int   g_cur [N0];
__device__ int   g_deg [N0];
__device__ int   g_np  [N0];
__device__ int   g_bsums[128];

// ------------------ feature build ------------------------------------------
__global__ void feat_kernel(const int* __restrict__ x, const float* __restrict__ eg,
                            const float* __restrict__ ea, float* __restrict__ h24) {
    int n = blockIdx.x*blockDim.x + threadIdx.x;
    if (n >= N0) return;
    int g = x[n*4+0];
    int a = x[n*4+3];
    float* o = h24 + n*24;
    #pragma unroll
    for (int i = 0; i < 16; i++) o[i] = eg[g*16+i];
    // replicate jnp.concatenate([sin, cos], axis=0).reshape(-1,2) exactly
    #pragma unroll
    for (int c = 0; c < 2; c++) {
        int j = 2*n + c;
        float xv, yv;
        if (j < N0) {
            xv = sinf((float)x[j*4+1]*DIVC);
            yv = sinf((float)x[j*4+2]*DIVC);
        } else {
            int jj = j - N0;
            xv = cosf((float)x[jj*4+1]*DIVC);
            yv = cosf((float)x[jj*4+2]*DIVC);
        }
        o[16+c] = xv;
        o[18+c] = yv;
    }
    #pragma unroll
    for (int i = 0; i < 4; i++) o[20+i] = ea[a*4+i];
}

__global__ void copy_edges(const int* __restrict__ ei, int* __restrict__ es, int* __restrict__ ed) {
    int e = blockIdx.x*blockDim.x + threadIdx.x;
    if (e < E_TOT) { es[e] = ei[e]; ed[e] = ei[E_TOT + e]; }
}

// ------------------ CSR build ----------------------------------------------
__global__ void hist_kernel(const int* __restrict__ ed, int* __restrict__ deg) {
    for (int e = blockIdx.x*blockDim.x + threadIdx.x; e < E_TOT; e += gridDim.x*blockDim.x) {
        int d = ed[e];
        if (d >= 0) atomicAdd(&deg[d], 1);
    }
}

__global__ void scan_block_kernel(const int* __restrict__ in, int* __restrict__ out,
                                  int* __restrict__ bsums, int N) {
    __shared__ int sh[1024];
    int tid = threadIdx.x;
    int gid = blockIdx.x*1024 + tid;
    int v = (gid < N) ? in[gid] : 0;
    sh[tid] = v;
    __syncthreads();
    for (int off = 1; off < 1024; off <<= 1) {
        int t = (tid >= off) ? sh[tid-off] : 0;
        __syncthreads();
        sh[tid] += t;
        __syncthreads();
    }
    if (gid < N) out[gid] = sh[tid] - v;           // exclusive within block
    if (tid == 1023) bsums[blockIdx.x] = sh[1023]; // block total
}

__global__ void scan_sums_kernel(int* __restrict__ bsums) {
    __shared__ int sh[128];
    int tid = threadIdx.x;
    int v = bsums[tid];
    sh[tid] = v;
    __syncthreads();
    for (int off = 1; off < 128; off <<= 1) {
        int t = (tid >= off) ? sh[tid-off] : 0;
        __syncthreads();
        sh[tid] += t;
        __syncthreads();
    }
    bsums[tid] = sh[tid] - v; // exclusive
}

__global__ void finalize_kernel(int* __restrict__ coff, int* __restrict__ cur,
                                float* __restrict__ dinv, const int* __restrict__ deg,
                                const int* __restrict__ bsums, int N) {
    int n = blockIdx.x*1024 + threadIdx.x;
    if (n >= N) return;
    int off = coff[n] + bsums[blockIdx.x];
    coff[n] = off;
    cur[n]  = off;
    dinv[n] = rsqrtf((float)deg[n] + 1.0f);
}

__global__ void scatter_kernel(const int* __restrict__ es, const int* __restrict__ ed,
                               int* __restrict__ cur, int* __restrict__ col) {
    for (int e = blockIdx.x*blockDim.x + threadIdx.x; e < E_TOT; e += gridDim.x*blockDim.x) {
        int d = ed[e];
        if (d >= 0) {
            int p = atomicAdd(&cur[d], 1);
            col[p] = es[e];
        }
    }
}

// ------------------ GCN kernels --------------------------------------------
// hd[n] = act(h[n]) @ W * dinv[n]
template<int INW, bool RELU>
__global__ void mm_kernel(const float* __restrict__ h, const float* __restrict__ W,
                          const float* __restrict__ dinv, float* __restrict__ hd, int N) {
    __shared__ float Ws[INW*16];
    for (int i = threadIdx.x; i < INW*16; i += blockDim.x) Ws[i] = W[i];
    __syncthreads();
    int n = blockIdx.x*blockDim.x + threadIdx.x;
    if (n >= N) return;
    float acc[16];
    #pragma unroll
    for (int j = 0; j < 16; j++) acc[j] = 0.f;
    const float* hr = h + (size_t)n*INW;
    #pragma unroll
    for (int i = 0; i < INW; i++) {
        float v = hr[i];
        if (RELU) v = fmaxf(v, 0.f);
        #pragma unroll
        for (int j = 0; j < 16; j++) acc[j] = fmaf(v, Ws[i*16+j], acc[j]);
    }
    float dv = dinv[n];
    float* o = hd + (size_t)n*16;
    #pragma unroll
    for (int j = 0; j < 16; j++) o[j] = acc[j]*dv;
}

// h_out[n] = dinv[n]*(hd[n] + sum_{e in CSR(n)} hd[col[e]]) + b
__global__ void agg_kernel(const float* __restrict__ hd, const int* __restrict__ coff,
                           const int* __restrict__ deg, const int* __restrict__ col,
                           const float* __restrict__ dinv, const float* __restrict__ b,
                           float* __restrict__ hout, int N) {
    int warp = (blockIdx.x*blockDim.x + threadIdx.x) >> 5;
    int lane = threadIdx.x & 31;
    if (warp >= N) return;
    int n = warp;
    int f  = lane & 15;
    int eh = lane >> 4;
    int start = coff[n];
    int cnt   = deg[n];
    float acc = 0.f;
    for (int i = eh; i < cnt; i += 2) {
        int s = col[start + i];
        acc += hd[(size_t)s*16 + f];
    }
    acc += __shfl_xor_sync(0xffffffffu, acc, 16);
    if (lane < 16) {
        float r = dinv[n]*(acc + hd[(size_t)n*16 + f]) + b[f];
        hout[(size_t)n*16 + f] = r;
    }
}

// ------------------ top-k pooling ------------------------------------------
template<int NPGv, int Kv, int Pv>
__global__ void pool_kernel(const float* __restrict__ h, const float* __restrict__ w,
                            float* __restrict__ hout, int* __restrict__ np) {
    __shared__ float skey[Pv];
    __shared__ int   sidx[Pv];
    int bG = blockIdx.x;
    int tid = threadIdx.x;
    const int T = 1024;
    float wn = 0.f;
    #pragma unroll
    for (int j = 0; j < 16; j++) { float wv = w[j]; wn = fmaf(wv, wv, wn); }
    wn = sqrtf(wn);
    for (int i = tid; i < Pv; i += T) {
        if (i < NPGv) {
            const float* hr = h + ((size_t)bG*NPGv + i)*16;
            float s = 0.f;
            #pragma unroll
            for (int j = 0; j < 16; j++) s = fmaf(hr[j], w[j], s);
            skey[i] = s/wn;
        } else {
            skey[i] = -FLT_MAX;
        }
        sidx[i] = i;
    }
    __syncthreads();
    // bitonic sort, descending
    for (int size = 2; size <= Pv; size <<= 1) {
        for (int stride = size >> 1; stride > 0; stride >>= 1) {
            for (int i = tid; i < Pv; i += T) {
                int p = i ^ stride;
                if (p > i) {
                    bool desc = ((i & size) == 0);
                    float a = skey[i], c = skey[p];
                    bool sw = desc ? (a < c) : (a > c);
                    if (sw) {
                        skey[i] = c; skey[p] = a;
                        int t = sidx[i]; sidx[i] = sidx[p]; sidx[p] = t;
                    }
                }
            }
            __syncthreads();
        }
    }
    for (int i = tid; i < NPGv; i += T) np[bG*NPGv + i] = -1;
    __syncthreads();
    for (int j = tid; j < Kv; j += T) np[bG*NPGv + sidx[j]] = bG*Kv + j;
    for (int t = tid; t < Kv*16; t += T) {
        int j = t >> 4, f = t & 15;
        float gate = tanhf(skey[j]);
        hout[((size_t)bG*Kv + j)*16 + f] = h[((size_t)bG*NPGv + sidx[j])*16 + f]*gate;
    }
}

__global__ void remap_kernel(int* __restrict__ es, int* __restrict__ ed,
                             const int* __restrict__ np) {
    int e = blockIdx.x*blockDim.x + threadIdx.x;
    if (e >= E_TOT) return;
    int s = es[e], d = ed[e];
    if (s >= 0 && d >= 0) {
        int ns = np[s], nd = np[d];
        if (ns >= 0 && nd >= 0) { es[e] = ns; ed[e] = nd; return; }
    }
    es[e] = -1; ed[e] = -1;
}

// ------------------ final mean-pool + linear --------------------------------
__global__ void final_kernel(const float* __restrict__ h, const float* __restrict__ linW,
                             const float* __restrict__ linb, float* __restrict__ out) {
    __shared__ float sh[128*16];
    int bG = blockIdx.x, tid = threadIdx.x;
    float acc[16];
    #pragma unroll
    for (int j = 0; j < 16; j++) acc[j] = 0.f;
    for (int r = tid; r < KK3; r += 128) {
        const float* hr = h + ((size_t)bG*KK3 + r)*16;
        #pragma unroll
        for (int j = 0; j < 16; j++) acc[j] += hr[j];
    }
    #pragma unroll
    for (int j = 0; j < 16; j++) sh[tid*16+j] = acc[j];
    __syncthreads();
    for (int s = 64; s > 0; s >>= 1) {
        if (tid < s) {
            #pragma unroll
            for (int j = 0; j < 16; j++) sh[tid*16+j] += sh[(tid+s)*16+j];
        }
        __syncthreads();
    }
    if (tid < OUTD) {
        float r = linb[tid];
        #pragma unroll
        for (int j = 0; j < 16; j++) r = fmaf(sh[j]/(float)KK3, linW[j*OUTD+tid], r);
        out[bG*OUTD + tid] = r;
    }
}

// ------------------ host orchestration -------------------------------------
static void build_csr(int N, int* esrc, int* edst, int* col, int* coff, int* cur,
                      int* deg, float* dinv, int* bsums) {
    int nb = (N + 1023)/1024;
    cudaMemsetAsync(deg, 0, (size_t)N*sizeof(int));
    cudaMemsetAsync(bsums, 0, 128*sizeof(int));
    hist_kernel<<<2048, 512>>>(edst, deg);
    scan_block_kernel<<<nb, 1024>>>(deg, coff, bsums, N);
    scan_sums_kernel<<<1, 128>>>(bsums);
    finalize_kernel<<<nb, 1024>>>(coff, cur, dinv, deg, bsums, N);
    scatter_kernel<<<2048, 512>>>(esrc, edst, cur, col);
}

extern "C" void kernel_launch(void* const* d_in, const int* in_sizes, int n_in,
                              void* d_out, int out_size) {
    const int*   x      = (const int*)  d_in[0];
    const int*   ei     = (const int*)  d_in[1];
    const float* eg     = (const float*)d_in[3];
    const float* ea     = (const float*)d_in[4];
    const float* firstW = (const float*)d_in[5];
    const float* firstb = (const float*)d_in[6];
    const float* Ws     = (const float*)d_in[7];
    const float* bs     = (const float*)d_in[8];
    const float* poolw  = (const float*)d_in[9];
    const float* linW   = (const float*)d_in[10];
    const float* linb   = (const float*)d_in[11];
    float* out = (float*)d_out;

    float *h24, *hd, *hA, *hB, *dinv;
    int *esrc, *edst, *col, *coff, *cur, *deg, *np, *bsums;
    cudaGetSymbolAddress((void**)&h24,  g_h24);
    cudaGetSymbolAddress((void**)&hd,   g_hd);
    cudaGetSymbolAddress((void**)&hA,   g_hA);
    cudaGetSymbolAddress((void**)&hB,   g_hB);
    cudaGetSymbolAddress((void**)&dinv, g_dinv);
    cudaGetSymbolAddress((void**)&esrc, g_esrc);
    cudaGetSymbolAddress((void**)&edst, g_edst);
    cudaGetSymbolAddress((void**)&col,  g_col);
    cudaGetSymbolAddress((void**)&coff, g_coff);
    cudaGetSymbolAddress((void**)&cur,  g_cur);
    cudaGetSymbolAddress((void**)&deg,  g_deg);
    cudaGetSymbolAddress((void**)&np,   g_np);
    cudaGetSymbolAddress((void**)&bsums,g_bsums);

    feat_kernel<<<(N0+127)/128, 128>>>(x, eg, ea, h24);
    copy_edges<<<(E_TOT+255)/256, 256>>>(ei, esrc, edst);

    build_csr(N0, esrc, edst, col, coff, cur, deg, dinv, bsums);

    // first GCN (24 -> 16, no relu)
    mm_kernel<24, false><<<(N0+127)/128, 128>>>(h24, firstW, dinv, hd, N0);
    agg_kernel<<<(N0+7)/8, 256>>>(hd, coff, deg, col, dinv, firstb, hA, N0);

    int li = 0;
    // block 0: 5 layers at N0
    for (int l = 0; l < 5; l++, li++) {
        mm_kernel<16, true><<<(N0+127)/128, 128>>>(hA, Ws + li*256, dinv, hd, N0);
        agg_kernel<<<(N0+7)/8, 256>>>(hd, coff, deg, col, dinv, bs + li*16, hA, N0);
    }
    pool_kernel<NPG0, KK1, 4096><<<BB, 1024>>>(hA, poolw + 0, hB, np);
    remap_kernel<<<(E_TOT+255)/256, 256>>>(esrc, edst, np);
    build_csr(NN1, esrc, edst, col, coff, cur, deg, dinv, bsums);

    // block 1: 5 layers at N1
    for (int l = 0; l < 5; l++, li++) {
        mm_kernel<16, true><<<(NN1+127)/128, 128>>>(hB, Ws + li*256, dinv, hd, NN1);
        agg_kernel<<<(NN1+7)/8, 256>>>(hd, coff, deg, col, dinv, bs + li*16, hB, NN1);
    }
    pool_kernel<KK1, KK2, 4096><<<BB, 1024>>>(hB, poolw + 16, hA, np);
    remap_kernel<<<(E_TOT+255)/256, 256>>>(esrc, edst, np);
    build_csr(NN2, esrc, edst, col, coff, cur, deg, dinv, bsums);

    // block 2: 5 layers at N2
    for (int l = 0; l < 5; l++, li++) {
        mm_kernel<16, true><<<(NN2+127)/128, 128>>>(hA, Ws + li*256, dinv, hd, NN2);
        agg_kernel<<<(NN2+7)/8, 256>>>(hd, coff, deg, col, dinv, bs + li*16, hA, NN2);
    }
    pool_kernel<KK2, KK3, 2048><<<BB, 1024>>>(hA, poolw + 32, hB, np);

    final_kernel<<<BB, 128>>>(hB, linW, linb, out);
}